// round 1
// baseline (speedup 1.0000x reference)
#include <cuda_runtime.h>
#include <cuda_bf16.h>
#include <mma.h>
#include <math.h>

using namespace nvcuda;

// ---------------- problem constants ----------------
#define B_   32
#define P_   2048
#define D_   1024
#define TD_  768
#define PR_  512
#define EPS_ 1e-5f

// ---------------- device scratch (no cudaMalloc allowed) ----------------
__device__ float g_q[(size_t)B_ * P_ * D_];        // 256 MB
__device__ float g_k[(size_t)B_ * P_ * D_];        // 256 MB
__device__ float g_v[(size_t)B_ * P_ * D_];        // 256 MB
__device__ float g_scores[(size_t)B_ * P_ * P_];   // 512 MB (attn written in-place)
__device__ float g_weighted[B_ * D_];
__device__ float g_feats[4 * B_ * PR_];            // [job][32][512]

// ---------------- WMMA tf32 GEMM, CTA tile 128x64, 8 warps (4x2), warp 32x32 ----------------
#define LDA_S 20   // 16 + 4 pad  (multiple of 4 elems = 16B)
#define LDB_S 68   // 64 + 4 pad

// mode 0: C = A@B + bias          (B is [K,N] row-major)
// mode 1: C = (A@Bt^T) * scale    (Bt is [N,K] row-major, i.e. k-matrix)
template <int MODE>
__device__ __forceinline__ void gemm_tile(
    const float* __restrict__ A, const float* __restrict__ Bsrc,
    const float* __restrict__ bias, float scale,
    float* __restrict__ C, int K, int Nld, int ldc,
    int m0, int n0)
{
    __shared__ __align__(16) float As[128 * LDA_S];
    __shared__ __align__(16) float Bs[16 * LDB_S];

    const int tid = threadIdx.x;
    const int wid = tid >> 5, lane = tid & 31;
    const int wm = wid >> 1, wn = wid & 1;

    wmma::fragment<wmma::accumulator, 16, 16, 8, float> acc[2][2];
#pragma unroll
    for (int i = 0; i < 2; i++)
#pragma unroll
        for (int j = 0; j < 2; j++) wmma::fill_fragment(acc[i][j], 0.0f);

    for (int kb = 0; kb < K; kb += 16) {
        __syncthreads();
        // A tile: 128x16 floats = 512 float4
#pragma unroll
        for (int t = tid; t < 512; t += 256) {
            int r = t >> 2, c4 = t & 3;
            float4 val = *(const float4*)(A + (size_t)(m0 + r) * K + kb + c4 * 4);
            *(float4*)(As + r * LDA_S + c4 * 4) = val;
        }
        // B tile: Bs[kk][n]
        if (MODE == 0) {
            if (tid < 256) {
                int r = tid >> 4, c4 = tid & 15;
                float4 val = *(const float4*)(Bsrc + (size_t)(kb + r) * Nld + n0 + c4 * 4);
                *(float4*)(Bs + r * LDB_S + c4 * 4) = val;
            }
        } else {
            if (tid < 256) {
                int n = tid >> 2, c4 = tid & 3;
                float4 val = *(const float4*)(Bsrc + (size_t)(n0 + n) * K + kb + c4 * 4);
                Bs[(c4 * 4 + 0) * LDB_S + n] = val.x;
                Bs[(c4 * 4 + 1) * LDB_S + n] = val.y;
                Bs[(c4 * 4 + 2) * LDB_S + n] = val.z;
                Bs[(c4 * 4 + 3) * LDB_S + n] = val.w;
            }
        }
        __syncthreads();

#pragma unroll
        for (int kk = 0; kk < 16; kk += 8) {
            wmma::fragment<wmma::matrix_a, 16, 16, 8, wmma::precision::tf32, wmma::row_major> af[2];
            wmma::fragment<wmma::matrix_b, 16, 16, 8, wmma::precision::tf32, wmma::row_major> bf[2];
#pragma unroll
            for (int mi = 0; mi < 2; mi++) {
                wmma::load_matrix_sync(af[mi], As + (wm * 32 + mi * 16) * LDA_S + kk, LDA_S);
#pragma unroll
                for (int t = 0; t < af[mi].num_elements; t++)
                    af[mi].x[t] = wmma::__float_to_tf32(af[mi].x[t]);
            }
#pragma unroll
            for (int ni = 0; ni < 2; ni++) {
                wmma::load_matrix_sync(bf[ni], Bs + kk * LDB_S + wn * 32 + ni * 16, LDB_S);
#pragma unroll
                for (int t = 0; t < bf[ni].num_elements; t++)
                    bf[ni].x[t] = wmma::__float_to_tf32(bf[ni].x[t]);
            }
#pragma unroll
            for (int mi = 0; mi < 2; mi++)
#pragma unroll
                for (int ni = 0; ni < 2; ni++)
                    wmma::mma_sync(acc[mi][ni], af[mi], bf[ni], acc[mi][ni]);
        }
    }

    // epilogue: stage each 16x16 frag through smem (reuse As)
    __syncthreads();
    float* stage = As + wid * 256;
#pragma unroll
    for (int mi = 0; mi < 2; mi++)
#pragma unroll
        for (int ni = 0; ni < 2; ni++) {
            wmma::store_matrix_sync(stage, acc[mi][ni], 16, wmma::mem_row_major);
            __syncwarp();
            int gm = m0 + wm * 32 + mi * 16;
            int gn = n0 + wn * 32 + ni * 16;
#pragma unroll
            for (int e = lane; e < 256; e += 32) {
                int r = e >> 4, c = e & 15;
                float vv = stage[e];
                if (MODE == 0) vv += bias[gn + c];
                else           vv *= scale;
                C[(size_t)(gm + r) * ldc + gn + c] = vv;
            }
            __syncwarp();
        }
}

__global__ __launch_bounds__(256) void gemm_qkv_kernel(
    const float* __restrict__ X,
    const float* __restrict__ Wq, const float* __restrict__ Wk, const float* __restrict__ Wv,
    const float* __restrict__ bq, const float* __restrict__ bk, const float* __restrict__ bv,
    float* __restrict__ q, float* __restrict__ k, float* __restrict__ v)
{
    int z = blockIdx.z;
    const float* W = (z == 0) ? Wq : (z == 1) ? Wk : Wv;
    const float* b = (z == 0) ? bq : (z == 1) ? bk : bv;
    float* C = (z == 0) ? q : (z == 1) ? k : v;
    gemm_tile<0>(X, W, b, 0.f, C, D_, D_, D_, blockIdx.y * 128, blockIdx.x * 64);
}

__global__ __launch_bounds__(256) void gemm_scores_kernel(
    const float* __restrict__ q, const float* __restrict__ k,
    float* __restrict__ sc, float scale)
{
    int b = blockIdx.z;
    const float* A = q + (size_t)b * P_ * D_;
    const float* Bt = k + (size_t)b * P_ * D_;
    float* C = sc + (size_t)b * P_ * P_;
    gemm_tile<1>(A, Bt, nullptr, scale, C, D_, 0, P_, blockIdx.y * 128, blockIdx.x * 64);
}

// ---------------- softmax over rows, in place (one warp per row) ----------------
__global__ __launch_bounds__(256) void softmax_rows_kernel(float* __restrict__ sc)
{
    int b = blockIdx.y;
    int wid = threadIdx.x >> 5, lane = threadIdx.x & 31;
    int row = blockIdx.x * 8 + wid;
    float* rp = sc + ((size_t)b * P_ + row) * P_;

    float vals[64];
#pragma unroll
    for (int i = 0; i < 64; i++) vals[i] = rp[lane + 32 * i];

    float m = -INFINITY;
#pragma unroll
    for (int i = 0; i < 64; i++) m = fmaxf(m, vals[i]);
#pragma unroll
    for (int o = 16; o > 0; o >>= 1) m = fmaxf(m, __shfl_xor_sync(0xFFFFFFFFu, m, o));

    float s = 0.f;
#pragma unroll
    for (int i = 0; i < 64; i++) { vals[i] = __expf(vals[i] - m); s += vals[i]; }
#pragma unroll
    for (int o = 16; o > 0; o >>= 1) s += __shfl_xor_sync(0xFFFFFFFFu, s, o);

    float rinv = 1.f / s;
#pragma unroll
    for (int i = 0; i < 64; i++) rp[lane + 32 * i] = vals[i] * rinv;
}

// ---------------- column mean of attn -> attn_weights (directly into d_out) ----------------
__global__ __launch_bounds__(256) void colsum_kernel(const float* __restrict__ sc, float* __restrict__ aw)
{
    int b = blockIdx.y;
    int q = blockIdx.x * 256 + threadIdx.x;
    const float* base = sc + (size_t)b * P_ * P_ + q;
    float acc = 0.f;
    for (int p = 0; p < P_; p++) acc += base[(size_t)p * P_];
    aw[b * P_ + q] = acc * (1.f / (float)P_);
}

// ---------------- weighted = aw @ v ----------------
__global__ void zero_kernel(float* p) { p[blockIdx.x * blockDim.x + threadIdx.x] = 0.f; }

__global__ __launch_bounds__(1024) void weighted_kernel(
    const float* __restrict__ aw, const float* __restrict__ v, float* __restrict__ wt)
{
    int b = blockIdx.y;
    int qc = blockIdx.x * 256;
    __shared__ float s_aw[256];
    if (threadIdx.x < 256) s_aw[threadIdx.x] = aw[b * P_ + qc + threadIdx.x];
    __syncthreads();
    float acc = 0.f;
    const float* vb = v + ((size_t)b * P_ + qc) * D_ + threadIdx.x;
#pragma unroll 4
    for (int qq = 0; qq < 256; qq++) acc += s_aw[qq] * vb[(size_t)qq * D_];
    atomicAdd(&wt[b * D_ + threadIdx.x], acc);
}

// ---------------- fused MLP + L2 normalize (one CTA per (sample, job)) ----------------
__device__ __forceinline__ float block_sum(float v, float* red)
{
#pragma unroll
    for (int o = 16; o > 0; o >>= 1) v += __shfl_xor_sync(0xFFFFFFFFu, v, o);
    int w = threadIdx.x >> 5, l = threadIdx.x & 31;
    if (l == 0) red[w] = v;
    __syncthreads();
    if (w == 0) {
        float r = (threadIdx.x < (blockDim.x >> 5)) ? red[threadIdx.x] : 0.f;
#pragma unroll
        for (int o = 16; o > 0; o >>= 1) r += __shfl_xor_sync(0xFFFFFFFFu, r, o);
        if (l == 0) red[0] = r;
    }
    __syncthreads();
    float out = red[0];
    __syncthreads();
    return out;
}

__global__ __launch_bounds__(1024) void mlp_kernel(
    const float* __restrict__ wt, const float* __restrict__ thum, const float* __restrict__ text,
    const float* peW1, const float* peb1, const float* peg, const float* pebt,
    const float* peW2, const float* peb2,
    const float* teW1, const float* teb1, const float* teg, const float* tebt,
    const float* teW2, const float* teb2,
    const float* thW1, const float* thb1, const float* thg, const float* thbt,
    const float* thW2, const float* thb2,
    float* __restrict__ feats)
{
    int row = blockIdx.x, job = blockIdx.y;
    const float *x, *W1, *b1, *g, *bt, *W2, *b2;
    int din;
    if (job == 0)      { x = wt + row * D_;                din = D_;  W1 = peW1; b1 = peb1; g = peg; bt = pebt; W2 = peW2; b2 = peb2; }
    else if (job == 1) { x = thum + row * D_;              din = D_;  W1 = thW1; b1 = thb1; g = thg; bt = thbt; W2 = thW2; b2 = thb2; }
    else if (job == 2) { x = text + row * 3 * TD_ + TD_;   din = TD_; W1 = teW1; b1 = teb1; g = teg; bt = tebt; W2 = teW2; b2 = teb2; }
    else               { x = text + row * 3 * TD_ + 2*TD_; din = TD_; W1 = teW1; b1 = teb1; g = teg; bt = tebt; W2 = teW2; b2 = teb2; }

    __shared__ float xs[1024];
    __shared__ float hs[1024];
    __shared__ float red[32];
    int tid = threadIdx.x;
    if (tid < din) xs[tid] = x[tid];
    __syncthreads();

    float acc = b1[tid];
    for (int i = 0; i < din; i++) acc += xs[i] * W1[(size_t)i * 1024 + tid];
    float h = fmaxf(acc, 0.f);

    float s1 = block_sum(h, red);
    float s2 = block_sum(h * h, red);
    float mu = s1 * (1.f / 1024.f);
    float var = s2 * (1.f / 1024.f) - mu * mu;
    float rstd = rsqrtf(var + EPS_);
    hs[tid] = (h - mu) * rstd * g[tid] + bt[tid];
    __syncthreads();

    float o = 0.f;
    if (tid < PR_) {
        float a2 = b2[tid];
        for (int i = 0; i < 1024; i++) a2 += hs[i] * W2[(size_t)i * PR_ + tid];
        o = fmaxf(a2, 0.f);
    }
    float nrm = block_sum(o * o, red);
    if (tid < PR_) feats[((size_t)job * B_ + row) * PR_ + tid] = o * rsqrtf(nrm);
}

// ---------------- logits ----------------
__global__ void logits_kernel(const float* __restrict__ feats, const float* __restrict__ ls_p,
                              float* __restrict__ out)
{
    int j = threadIdx.x, i = threadIdx.y;
    float ls = expf(ls_p[0]);
    const float* pf = feats;                 // patch_features
    const float* tf = feats + 1 * B_ * PR_;  // thum_features
    const float* of = feats + 2 * B_ * PR_;  // text_orgp
    const float* hf = feats + 3 * B_ * PR_;  // text_hist
    float lt = 0.f, lp = 0.f;
    for (int d = 0; d < PR_; d++) {
        lt += tf[i * PR_ + d] * of[j * PR_ + d];
        lp += pf[i * PR_ + d] * hf[j * PR_ + d];
    }
    lt *= ls; lp *= ls;
    out[0 * 1024 + i * 32 + j] = lt;
    out[1 * 1024 + i * 32 + j] = lp;
    out[2 * 1024 + j * 32 + i] = lt;
    out[3 * 1024 + j * 32 + i] = lp;
}

// ---------------- launch ----------------
extern "C" void kernel_launch(void* const* d_in, const int* in_sizes, int n_in,
                              void* d_out, int out_size)
{
    const float* thum  = (const float*)d_in[0];
    const float* patch = (const float*)d_in[1];
    const float* text  = (const float*)d_in[2];
    const float* Wq = (const float*)d_in[3];  const float* bq = (const float*)d_in[4];
    const float* Wk = (const float*)d_in[5];  const float* bk = (const float*)d_in[6];
    const float* Wv = (const float*)d_in[7];  const float* bv = (const float*)d_in[8];
    const float* peW1 = (const float*)d_in[9];  const float* peb1 = (const float*)d_in[10];
    const float* peg  = (const float*)d_in[11]; const float* pebt = (const float*)d_in[12];
    const float* peW2 = (const float*)d_in[13]; const float* peb2 = (const float*)d_in[14];
    const float* teW1 = (const float*)d_in[15]; const float* teb1 = (const float*)d_in[16];
    const float* teg  = (const float*)d_in[17]; const float* tebt = (const float*)d_in[18];
    const float* teW2 = (const float*)d_in[19]; const float* teb2 = (const float*)d_in[20];
    const float* thW1 = (const float*)d_in[21]; const float* thb1 = (const float*)d_in[22];
    const float* thg  = (const float*)d_in[23]; const float* thbt = (const float*)d_in[24];
    const float* thW2 = (const float*)d_in[25]; const float* thb2 = (const float*)d_in[26];
    const float* logit_scale = (const float*)d_in[27];

    float* out = (float*)d_out;
    float* aw_out = out + 4 * 1024;   // attn_weights region

    float *q, *k, *v, *sc, *wt, *ft;
    cudaGetSymbolAddress((void**)&q,  g_q);
    cudaGetSymbolAddress((void**)&k,  g_k);
    cudaGetSymbolAddress((void**)&v,  g_v);
    cudaGetSymbolAddress((void**)&sc, g_scores);
    cudaGetSymbolAddress((void**)&wt, g_weighted);
    cudaGetSymbolAddress((void**)&ft, g_feats);

    const float scale = 1.f / 32.f;  // 1/sqrt(1024)

    // 1) q,k,v = X @ W* + b*
    gemm_qkv_kernel<<<dim3(D_ / 64, (B_ * P_) / 128, 3), 256>>>(
        patch, Wq, Wk, Wv, bq, bk, bv, q, k, v);

    // 2) scores = q @ k^T * scale (batched)
    gemm_scores_kernel<<<dim3(P_ / 64, P_ / 128, B_), 256>>>(q, k, sc, scale);

    // 3) softmax over rows (in place)
    softmax_rows_kernel<<<dim3(P_ / 8, B_), 256>>>(sc);

    // 4) attn_weights = column mean -> directly into output
    colsum_kernel<<<dim3(P_ / 256, B_), 256>>>(sc, aw_out);

    // 5) weighted = attn_weights @ v
    zero_kernel<<<B_, D_>>>(wt);
    weighted_kernel<<<dim3(P_ / 256, B_), 1024>>>(aw_out, v, wt);

    // 6) four MLPs + L2 normalize
    mlp_kernel<<<dim3(B_, 4), 1024>>>(wt, thum, text,
        peW1, peb1, peg, pebt, peW2, peb2,
        teW1, teb1, teg, tebt, teW2, teb2,
        thW1, thb1, thg, thbt, thW2, thb2, ft);

    // 7) logits (all 4 views)
    logits_kernel<<<1, dim3(32, 32)>>>(ft, logit_scale, out);
}

// round 2
// speedup vs baseline: 1.3394x; 1.3394x over previous
#include <cuda_runtime.h>
#include <cuda_bf16.h>
#include <mma.h>
#include <math.h>

using namespace nvcuda;

// ---------------- problem constants ----------------
#define B_   32
#define P_   2048
#define D_   1024
#define TD_  768
#define PR_  512
#define EPS_ 1e-5f

// ---------------- device scratch (no cudaMalloc allowed) ----------------
__device__ __nv_bfloat16 g_qh[(size_t)B_ * P_ * D_];   // 128 MB
__device__ __nv_bfloat16 g_kh[(size_t)B_ * P_ * D_];   // 128 MB
__device__ float         g_v [(size_t)B_ * P_ * D_];   // 256 MB
__device__ float g_scores[(size_t)B_ * P_ * P_];       // 512 MB (attn in-place)
__device__ float g_weighted[B_ * D_];
__device__ float g_feats[4 * B_ * PR_];

// ============================================================
// GEMM 1: qkv = X @ W + b   (tf32, 128x128 CTA tile, K-tile 16,
// double-buffered, register prefetch). q,k written as bf16, v as f32.
// X: [65536,1024] f32, W: [1024,1024] f32.
// ============================================================
#define G1_LDA 20    // 16 + 4 pad
#define G1_LDB 132   // 128 + 4 pad

__global__ __launch_bounds__(256) void gemm_qkv_kernel(
    const float* __restrict__ X,
    const float* __restrict__ Wq, const float* __restrict__ Wk, const float* __restrict__ Wv,
    const float* __restrict__ bq, const float* __restrict__ bk, const float* __restrict__ bv,
    __nv_bfloat16* __restrict__ qh, __nv_bfloat16* __restrict__ kh,
    float* __restrict__ v)
{
    __shared__ __align__(16) float As[2][128 * G1_LDA];
    __shared__ __align__(16) float Bs[2][16 * G1_LDB];

    const int z = blockIdx.z;
    const float* W = (z == 0) ? Wq : (z == 1) ? Wk : Wv;
    const float* bias = (z == 0) ? bq : (z == 1) ? bk : bv;

    const int m0 = blockIdx.y * 128;
    const int n0 = blockIdx.x * 128;

    const int tid = threadIdx.x;
    const int wid = tid >> 5, lane = tid & 31;
    const int wm = wid >> 2;      // 0..1 -> 64 rows each
    const int wn = wid & 3;       // 0..3 -> 32 cols each

    wmma::fragment<wmma::accumulator, 16, 16, 8, float> acc[4][2];
#pragma unroll
    for (int i = 0; i < 4; i++)
#pragma unroll
        for (int j = 0; j < 2; j++) wmma::fill_fragment(acc[i][j], 0.0f);

    // indices for cooperative loads (2 float4 each for A and B per stage)
    const int ar0 = tid >> 2,        ac0 = (tid & 3) * 4;        // A: t in [0,256)
    const int ar1 = (tid + 256) >> 2, ac1 = ((tid + 256) & 3) * 4;
    const int br0 = tid >> 5,        bc0 = (tid & 31) * 4;       // B: t in [0,256)
    const int br1 = (tid + 256) >> 5, bc1 = ((tid + 256) & 31) * 4;

    // preload tile 0
    {
        *(float4*)(&As[0][ar0 * G1_LDA + ac0]) = *(const float4*)(X + (size_t)(m0 + ar0) * D_ + ac0);
        *(float4*)(&As[0][ar1 * G1_LDA + ac1]) = *(const float4*)(X + (size_t)(m0 + ar1) * D_ + ac1);
        *(float4*)(&Bs[0][br0 * G1_LDB + bc0]) = *(const float4*)(W + (size_t)br0 * D_ + n0 + bc0);
        *(float4*)(&Bs[0][br1 * G1_LDB + bc1]) = *(const float4*)(W + (size_t)br1 * D_ + n0 + bc1);
    }
    __syncthreads();

    const int T = D_ / 16;
    int buf = 0;
    float4 pa0, pa1, pb0, pb1;
    for (int t = 0; t < T; t++) {
        const int kb_next = (t + 1) * 16;
        if (t + 1 < T) {
            pa0 = *(const float4*)(X + (size_t)(m0 + ar0) * D_ + kb_next + ac0);
            pa1 = *(const float4*)(X + (size_t)(m0 + ar1) * D_ + kb_next + ac1);
            pb0 = *(const float4*)(W + (size_t)(kb_next + br0) * D_ + n0 + bc0);
            pb1 = *(const float4*)(W + (size_t)(kb_next + br1) * D_ + n0 + bc1);
        }
#pragma unroll
        for (int kk = 0; kk < 16; kk += 8) {
            wmma::fragment<wmma::matrix_a, 16, 16, 8, wmma::precision::tf32, wmma::row_major> af[4];
            wmma::fragment<wmma::matrix_b, 16, 16, 8, wmma::precision::tf32, wmma::row_major> bf[2];
#pragma unroll
            for (int mi = 0; mi < 4; mi++) {
                wmma::load_matrix_sync(af[mi], &As[buf][(wm * 64 + mi * 16) * G1_LDA + kk], G1_LDA);
#pragma unroll
                for (int e = 0; e < af[mi].num_elements; e++)
                    af[mi].x[e] = wmma::__float_to_tf32(af[mi].x[e]);
            }
#pragma unroll
            for (int ni = 0; ni < 2; ni++) {
                wmma::load_matrix_sync(bf[ni], &Bs[buf][kk * G1_LDB + wn * 32 + ni * 16], G1_LDB);
#pragma unroll
                for (int e = 0; e < bf[ni].num_elements; e++)
                    bf[ni].x[e] = wmma::__float_to_tf32(bf[ni].x[e]);
            }
#pragma unroll
            for (int mi = 0; mi < 4; mi++)
#pragma unroll
                for (int ni = 0; ni < 2; ni++)
                    wmma::mma_sync(acc[mi][ni], af[mi], bf[ni], acc[mi][ni]);
        }
        if (t + 1 < T) {
            int nb = buf ^ 1;
            *(float4*)(&As[nb][ar0 * G1_LDA + ac0]) = pa0;
            *(float4*)(&As[nb][ar1 * G1_LDA + ac1]) = pa1;
            *(float4*)(&Bs[nb][br0 * G1_LDB + bc0]) = pb0;
            *(float4*)(&Bs[nb][br1 * G1_LDB + bc1]) = pb1;
        }
        __syncthreads();
        buf ^= 1;
    }

    // epilogue: stage per-warp 16x16 frags through smem, add bias, write
    float* stage = &As[0][0] + wid * 256;
#pragma unroll
    for (int mi = 0; mi < 4; mi++)
#pragma unroll
        for (int ni = 0; ni < 2; ni++) {
            wmma::store_matrix_sync(stage, acc[mi][ni], 16, wmma::mem_row_major);
            __syncwarp();
            int gm = m0 + wm * 64 + mi * 16;
            int gn = n0 + wn * 32 + ni * 16;
#pragma unroll
            for (int e = lane; e < 256; e += 32) {
                int r = e >> 4, c = e & 15;
                float val = stage[e] + bias[gn + c];
                size_t idx = (size_t)(gm + r) * D_ + gn + c;
                if (z == 0)      qh[idx] = __float2bfloat16(val);
                else if (z == 1) kh[idx] = __float2bfloat16(val);
                else             v[idx]  = val;
            }
            __syncwarp();
        }
}

// ============================================================
// GEMM 2: scores = q @ k^T   (bf16, per batch, 128x128 CTA tile,
// K-tile 32, double buffered). Raw accums to global; scale folded
// into softmax.
// ============================================================
#define G2_LD 40     // 32 + 8 pad (bf16 elems)

__global__ __launch_bounds__(256) void gemm_scores_kernel(
    const __nv_bfloat16* __restrict__ qh, const __nv_bfloat16* __restrict__ kh,
    float* __restrict__ sc)
{
    __shared__ __align__(16) __nv_bfloat16 As[2][128 * G2_LD];
    __shared__ __align__(16) __nv_bfloat16 Bs[2][128 * G2_LD];

    const int b = blockIdx.z;
    const __nv_bfloat16* A = qh + (size_t)b * P_ * D_;
    const __nv_bfloat16* Bk = kh + (size_t)b * P_ * D_;
    float* C = sc + (size_t)b * P_ * P_;

    const int m0 = blockIdx.y * 128;
    const int n0 = blockIdx.x * 128;

    const int tid = threadIdx.x;
    const int wid = tid >> 5;
    const int wm = wid >> 2, wn = wid & 3;

    wmma::fragment<wmma::accumulator, 16, 16, 16, float> acc[4][2];
#pragma unroll
    for (int i = 0; i < 4; i++)
#pragma unroll
        for (int j = 0; j < 2; j++) wmma::fill_fragment(acc[i][j], 0.0f);

    // tile = 128 rows x 32 bf16 = 1024 uint2 (4 bf16 each); 4 per thread
    // thread handles t = tid + 256*i : r = t>>3, c = (t&7)*4
#pragma unroll
    const int T = D_ / 32;
    // preload tile 0
#pragma unroll
    for (int i = 0; i < 4; i++) {
        int t = tid + 256 * i;
        int r = t >> 3, c = (t & 7) * 4;
        *(uint2*)(&As[0][r * G2_LD + c]) = *(const uint2*)(A + (size_t)(m0 + r) * D_ + c);
        *(uint2*)(&Bs[0][r * G2_LD + c]) = *(const uint2*)(Bk + (size_t)(n0 + r) * D_ + c);
    }
    __syncthreads();

    int buf = 0;
    uint2 pa[4], pb[4];
    for (int t = 0; t < T; t++) {
        const int kb_next = (t + 1) * 32;
        if (t + 1 < T) {
#pragma unroll
            for (int i = 0; i < 4; i++) {
                int tt = tid + 256 * i;
                int r = tt >> 3, c = (tt & 7) * 4;
                pa[i] = *(const uint2*)(A + (size_t)(m0 + r) * D_ + kb_next + c);
                pb[i] = *(const uint2*)(Bk + (size_t)(n0 + r) * D_ + kb_next + c);
            }
        }
#pragma unroll
        for (int kk = 0; kk < 32; kk += 16) {
            wmma::fragment<wmma::matrix_a, 16, 16, 16, __nv_bfloat16, wmma::row_major> af[4];
            wmma::fragment<wmma::matrix_b, 16, 16, 16, __nv_bfloat16, wmma::col_major> bf[2];
#pragma unroll
            for (int mi = 0; mi < 4; mi++)
                wmma::load_matrix_sync(af[mi], &As[buf][(wm * 64 + mi * 16) * G2_LD + kk], G2_LD);
#pragma unroll
            for (int ni = 0; ni < 2; ni++)
                wmma::load_matrix_sync(bf[ni], &Bs[buf][(wn * 32 + ni * 16) * G2_LD + kk], G2_LD);
#pragma unroll
            for (int mi = 0; mi < 4; mi++)
#pragma unroll
                for (int ni = 0; ni < 2; ni++)
                    wmma::mma_sync(acc[mi][ni], af[mi], bf[ni], acc[mi][ni]);
        }
        if (t + 1 < T) {
            int nb = buf ^ 1;
#pragma unroll
            for (int i = 0; i < 4; i++) {
                int tt = tid + 256 * i;
                int r = tt >> 3, c = (tt & 7) * 4;
                *(uint2*)(&As[nb][r * G2_LD + c]) = pa[i];
                *(uint2*)(&Bs[nb][r * G2_LD + c]) = pb[i];
            }
        }
        __syncthreads();
        buf ^= 1;
    }

    // epilogue: raw accumulators straight to global
#pragma unroll
    for (int mi = 0; mi < 4; mi++)
#pragma unroll
        for (int ni = 0; ni < 2; ni++) {
            int gm = m0 + wm * 64 + mi * 16;
            int gn = n0 + wn * 32 + ni * 16;
            wmma::store_matrix_sync(C + (size_t)gm * P_ + gn, acc[mi][ni], P_, wmma::mem_row_major);
        }
}

// ---------------- softmax over rows, in place (scale folded in) ----------------
__global__ __launch_bounds__(256) void softmax_rows_kernel(float* __restrict__ sc, float scale)
{
    int b = blockIdx.y;
    int wid = threadIdx.x >> 5, lane = threadIdx.x & 31;
    int row = blockIdx.x * 8 + wid;
    float* rp = sc + ((size_t)b * P_ + row) * P_;

    float vals[64];
#pragma unroll
    for (int i = 0; i < 64; i++) vals[i] = rp[lane + 32 * i] * scale;

    float m = -INFINITY;
#pragma unroll
    for (int i = 0; i < 64; i++) m = fmaxf(m, vals[i]);
#pragma unroll
    for (int o = 16; o > 0; o >>= 1) m = fmaxf(m, __shfl_xor_sync(0xFFFFFFFFu, m, o));

    float s = 0.f;
#pragma unroll
    for (int i = 0; i < 64; i++) { vals[i] = __expf(vals[i] - m); s += vals[i]; }
#pragma unroll
    for (int o = 16; o > 0; o >>= 1) s += __shfl_xor_sync(0xFFFFFFFFu, s, o);

    float rinv = 1.f / s;
#pragma unroll
    for (int i = 0; i < 64; i++) rp[lane + 32 * i] = vals[i] * rinv;
}

// ---------------- column mean of attn -> attn_weights ----------------
__global__ __launch_bounds__(256) void colsum_kernel(const float* __restrict__ sc, float* __restrict__ aw)
{
    int b = blockIdx.y;
    int q = blockIdx.x * 256 + threadIdx.x;
    const float* base = sc + (size_t)b * P_ * P_ + q;
    float acc = 0.f;
    for (int p = 0; p < P_; p++) acc += base[(size_t)p * P_];
    aw[b * P_ + q] = acc * (1.f / (float)P_);
}

// ---------------- weighted = aw @ v ----------------
__global__ void zero_kernel(float* p) { p[blockIdx.x * blockDim.x + threadIdx.x] = 0.f; }

__global__ __launch_bounds__(1024) void weighted_kernel(
    const float* __restrict__ aw, const float* __restrict__ v, float* __restrict__ wt)
{
    int b = blockIdx.y;
    int qc = blockIdx.x * 256;
    __shared__ float s_aw[256];
    if (threadIdx.x < 256) s_aw[threadIdx.x] = aw[b * P_ + qc + threadIdx.x];
    __syncthreads();
    float acc = 0.f;
    const float* vb = v + ((size_t)b * P_ + qc) * D_ + threadIdx.x;
#pragma unroll 4
    for (int qq = 0; qq < 256; qq++) acc += s_aw[qq] * vb[(size_t)qq * D_];
    atomicAdd(&wt[b * D_ + threadIdx.x], acc);
}

// ---------------- fused MLP + L2 normalize ----------------
__device__ __forceinline__ float block_sum(float v, float* red)
{
#pragma unroll
    for (int o = 16; o > 0; o >>= 1) v += __shfl_xor_sync(0xFFFFFFFFu, v, o);
    int w = threadIdx.x >> 5, l = threadIdx.x & 31;
    if (l == 0) red[w] = v;
    __syncthreads();
    if (w == 0) {
        float r = (threadIdx.x < (blockDim.x >> 5)) ? red[threadIdx.x] : 0.f;
#pragma unroll
        for (int o = 16; o > 0; o >>= 1) r += __shfl_xor_sync(0xFFFFFFFFu, r, o);
        if (l == 0) red[0] = r;
    }
    __syncthreads();
    float out = red[0];
    __syncthreads();
    return out;
}

__global__ __launch_bounds__(1024) void mlp_kernel(
    const float* __restrict__ wt, const float* __restrict__ thum, const float* __restrict__ text,
    const float* peW1, const float* peb1, const float* peg, const float* pebt,
    const float* peW2, const float* peb2,
    const float* teW1, const float* teb1, const float* teg, const float* tebt,
    const float* teW2, const float* teb2,
    const float* thW1, const float* thb1, const float* thg, const float* thbt,
    const float* thW2, const float* thb2,
    float* __restrict__ feats)
{
    int row = blockIdx.x, job = blockIdx.y;
    const float *x, *W1, *b1, *g, *bt, *W2, *b2;
    int din;
    if (job == 0)      { x = wt + row * D_;                din = D_;  W1 = peW1; b1 = peb1; g = peg; bt = pebt; W2 = peW2; b2 = peb2; }
    else if (job == 1) { x = thum + row * D_;              din = D_;  W1 = thW1; b1 = thb1; g = thg; bt = thbt; W2 = thW2; b2 = thb2; }
    else if (job == 2) { x = text + row * 3 * TD_ + TD_;   din = TD_; W1 = teW1; b1 = teb1; g = teg; bt = tebt; W2 = teW2; b2 = teb2; }
    else               { x = text + row * 3 * TD_ + 2*TD_; din = TD_; W1 = teW1; b1 = teb1; g = teg; bt = tebt; W2 = teW2; b2 = teb2; }

    __shared__ float xs[1024];
    __shared__ float hs[1024];
    __shared__ float red[32];
    int tid = threadIdx.x;
    if (tid < din) xs[tid] = x[tid];
    __syncthreads();

    float acc = b1[tid];
    for (int i = 0; i < din; i++) acc += xs[i] * W1[(size_t)i * 1024 + tid];
    float h = fmaxf(acc, 0.f);

    float s1 = block_sum(h, red);
    float s2 = block_sum(h * h, red);
    float mu = s1 * (1.f / 1024.f);
    float var = s2 * (1.f / 1024.f) - mu * mu;
    float rstd = rsqrtf(var + EPS_);
    hs[tid] = (h - mu) * rstd * g[tid] + bt[tid];
    __syncthreads();

    float o = 0.f;
    if (tid < PR_) {
        float a2 = b2[tid];
        for (int i = 0; i < 1024; i++) a2 += hs[i] * W2[(size_t)i * PR_ + tid];
        o = fmaxf(a2, 0.f);
    }
    float nrm = block_sum(o * o, red);
    if (tid < PR_) feats[((size_t)job * B_ + row) * PR_ + tid] = o * rsqrtf(nrm);
}

// ---------------- logits ----------------
__global__ void logits_kernel(const float* __restrict__ feats, const float* __restrict__ ls_p,
                              float* __restrict__ out)
{
    int j = threadIdx.x, i = threadIdx.y;
    float ls = expf(ls_p[0]);
    const float* pf = feats;                 // patch_features
    const float* tf = feats + 1 * B_ * PR_;  // thum_features
    const float* of = feats + 2 * B_ * PR_;  // text_orgp
    const float* hf = feats + 3 * B_ * PR_;  // text_hist
    float lt = 0.f, lp = 0.f;
    for (int d = 0; d < PR_; d++) {
        lt += tf[i * PR_ + d] * of[j * PR_ + d];
        lp += pf[i * PR_ + d] * hf[j * PR_ + d];
    }
    lt *= ls; lp *= ls;
    out[0 * 1024 + i * 32 + j] = lt;
    out[1 * 1024 + i * 32 + j] = lp;
    out[2 * 1024 + j * 32 + i] = lt;
    out[3 * 1024 + j * 32 + i] = lp;
}

// ---------------- launch ----------------
extern "C" void kernel_launch(void* const* d_in, const int* in_sizes, int n_in,
                              void* d_out, int out_size)
{
    const float* thum  = (const float*)d_in[0];
    const float* patch = (const float*)d_in[1];
    const float* text  = (const float*)d_in[2];
    const float* Wq = (const float*)d_in[3];  const float* bq = (const float*)d_in[4];
    const float* Wk = (const float*)d_in[5];  const float* bk = (const float*)d_in[6];
    const float* Wv = (const float*)d_in[7];  const float* bv = (const float*)d_in[8];
    const float* peW1 = (const float*)d_in[9];  const float* peb1 = (const float*)d_in[10];
    const float* peg  = (const float*)d_in[11]; const float* pebt = (const float*)d_in[12];
    const float* peW2 = (const float*)d_in[13]; const float* peb2 = (const float*)d_in[14];
    const float* teW1 = (const float*)d_in[15]; const float* teb1 = (const float*)d_in[16];
    const float* teg  = (const float*)d_in[17]; const float* tebt = (const float*)d_in[18];
    const float* teW2 = (const float*)d_in[19]; const float* teb2 = (const float*)d_in[20];
    const float* thW1 = (const float*)d_in[21]; const float* thb1 = (const float*)d_in[22];
    const float* thg  = (const float*)d_in[23]; const float* thbt = (const float*)d_in[24];
    const float* thW2 = (const float*)d_in[25]; const float* thb2 = (const float*)d_in[26];
    const float* logit_scale = (const float*)d_in[27];

    float* out = (float*)d_out;
    float* aw_out = out + 4 * 1024;   // attn_weights region

    __nv_bfloat16 *qh, *kh;
    float *v, *sc, *wt, *ft;
    cudaGetSymbolAddress((void**)&qh, g_qh);
    cudaGetSymbolAddress((void**)&kh, g_kh);
    cudaGetSymbolAddress((void**)&v,  g_v);
    cudaGetSymbolAddress((void**)&sc, g_scores);
    cudaGetSymbolAddress((void**)&wt, g_weighted);
    cudaGetSymbolAddress((void**)&ft, g_feats);

    const float scale = 1.f / 32.f;  // 1/sqrt(1024)

    // 1) q,k (bf16), v (f32) = X @ W* + b*
    gemm_qkv_kernel<<<dim3(D_ / 128, (B_ * P_) / 128, 3), 256>>>(
        patch, Wq, Wk, Wv, bq, bk, bv, qh, kh, v);

    // 2) scores = q @ k^T (raw; scale folded into softmax)
    gemm_scores_kernel<<<dim3(P_ / 128, P_ / 128, B_), 256>>>(qh, kh, sc);

    // 3) softmax over rows (in place, applies scale)
    softmax_rows_kernel<<<dim3(P_ / 8, B_), 256>>>(sc, scale);

    // 4) attn_weights = column mean -> directly into output
    colsum_kernel<<<dim3(P_ / 256, B_), 256>>>(sc, aw_out);

    // 5) weighted = attn_weights @ v
    zero_kernel<<<B_, D_>>>(wt);
    weighted_kernel<<<dim3(P_ / 256, B_), 1024>>>(aw_out, v, wt);

    // 6) four MLPs + L2 normalize
    mlp_kernel<<<dim3(B_, 4), 1024>>>(wt, thum, text,
        peW1, peb1, peg, pebt, peW2, peb2,
        teW1, teb1, teg, tebt, teW2, teb2,
        thW1, thb1, thg, thbt, thW2, thb2, ft);

    // 7) logits (all 4 views)
    logits_kernel<<<1, dim3(32, 32)>>>(ft, logit_scale, out);
}